// round 5
// baseline (speedup 1.0000x reference)
#include <cuda_runtime.h>
#include <cuda_fp16.h>

#define NB_ 16384
#define SCALE_ 0.17677669529663687f  // 1/sqrt(32)

typedef unsigned u32;

// ---- interleaved weight fragment buffers: uint4 = {b0_hi, b1_hi, b0_lo, b1_lo} ----
__device__ __align__(16) uint4 g_wqkv_i[48 * 8 * 32];  // 196608 B
__device__ __align__(16) uint4 g_wo_i[16 * 8 * 32];    //  65536 B

__device__ __forceinline__ void split_pair(float a, float b, u32& hi, u32& lo) {
    __half ha = __float2half_rn(a), hb = __float2half_rn(b);
    __half2 h2 = __halves2half2(ha, hb);
    hi = *(u32*)&h2;
    __half2 l2 = __floats2half2_rn(a - __half2float(ha), b - __half2float(hb));
    lo = *(u32*)&l2;
}
__device__ __forceinline__ void split_one(float v, __half* ph, __half* pl) {
    __half h = __float2half_rn(v);
    *ph = h;
    *pl = __float2half_rn(v - __half2float(h));
}

__device__ __forceinline__ void mma16816(float* d, const u32* a, const u32* b) {
    asm volatile(
        "mma.sync.aligned.m16n8k16.row.col.f32.f16.f16.f32 "
        "{%0,%1,%2,%3}, {%4,%5,%6,%7}, {%8,%9}, {%0,%1,%2,%3};\n"
        : "+f"(d[0]), "+f"(d[1]), "+f"(d[2]), "+f"(d[3])
        : "r"(a[0]), "r"(a[1]), "r"(a[2]), "r"(a[3]), "r"(b[0]), "r"(b[1]));
}
// A-fragment (m16k16 row-major halfs, row stride `stride` halfs); base pre-offset to [g][2*tig]
__device__ __forceinline__ void loadA(u32* fr, const __half* base, int stride) {
    fr[0] = *(const u32*)(base);
    fr[1] = *(const u32*)(base + 8 * stride);
    fr[2] = *(const u32*)(base + 8);
    fr[3] = *(const u32*)(base + 8 * stride + 8);
}

// ---- prep kernel: 16384 jobs, one uint4 each ----
__global__ void prep_weights(const float* __restrict__ wq, const float* __restrict__ wk,
                             const float* __restrict__ wv, const float* __restrict__ wo) {
    int i = blockIdx.x * blockDim.x + threadIdx.x;
    if (i < 12288) {  // qkv: i = (j*8+kt)*32 + lane
        int lane = i & 31, kt = (i >> 5) & 7, j = i >> 8;
        int tig = lane & 3, gg = lane >> 2;
        int m = j >> 4, h = (j >> 2) & 3, dt = j & 3;
        const float* w = ((m == 0) ? wq : ((m == 1) ? wk : wv)) + h * 4096;
        int d = dt * 8 + gg;
        int e0 = kt * 16 + 2 * tig;
        u32 h0, l0, h1, l1;
        split_pair(w[e0 * 32 + d], w[(e0 + 1) * 32 + d], h0, l0);
        split_pair(w[(e0 + 8) * 32 + d], w[(e0 + 9) * 32 + d], h1, l1);
        g_wqkv_i[i] = make_uint4(h0, h1, l0, l1);
    } else if (i < 16384) {  // wo: k = (nt*8+kt)*32 + lane
        int k = i - 12288;
        int lane = k & 31, kt = (k >> 5) & 7, nt = k >> 8;
        int tig = lane & 3, gg = lane >> 2;
        int o = nt * 8 + gg;
        int hd0 = kt * 16 + 2 * tig;
        u32 h0, l0, h1, l1;
        split_pair(wo[hd0 * 128 + o], wo[(hd0 + 1) * 128 + o], h0, l0);
        split_pair(wo[(hd0 + 8) * 128 + o], wo[(hd0 + 9) * 128 + o], h1, l1);
        g_wo_i[k] = make_uint4(h0, h1, l0, l1);
    }
}

// ---- smem layout (total 72192 B -> 3 CTAs/SM) ----
// Region0 [0,16896): time-multiplexed
//   X  (ph1):  32 rows x 264 halfs  (hi cols 0..127, lo at +128)
//   SC (ph2-3): float [4][32][33]
//   HD (ph4-5): 32 rows x 264 halfs (hi 0..127, lo at +128)
// Q  [16896,35328): [4][32][72] halfs (hi 0..31, lo at +32)
// K  [35328,53760): same; reused as A after phase 2
// VT [53760,72192): same, rows=d, cols=t
#define XSTR 264
#define QSTR 72
#define QHEAD 2304
#define OFF_Q 16896
#define OFF_K 35328
#define OFF_VT 53760
#define SMEM_BYTES 72192

extern __shared__ char smem_raw[];

__global__ __launch_bounds__(256, 3)
void attn_mma3_kernel(const float* __restrict__ x, float* __restrict__ out) {
    __half* X  = (__half*)(smem_raw);
    float*  SC = (float*)(smem_raw);
    __half* HD = (__half*)(smem_raw);
    __half* Q  = (__half*)(smem_raw + OFF_Q);
    __half* K  = (__half*)(smem_raw + OFF_K);
    __half* VT = (__half*)(smem_raw + OFF_VT);
    __half* A  = K;  // reuse after phase 2

    const int tid = threadIdx.x;
    const int lane = tid & 31, w = tid >> 5;
    const int g = lane >> 2, tig = lane & 3;
    const long long b = blockIdx.x;

    // ---- load x, split fp16 hi/lo into combined rows ----
    const float2* xb2 = (const float2*)(x + b * 4096LL);
#pragma unroll
    for (int i = 0; i < 8; i++) {
        int idx = tid + i * 256;  // s = idx/64, e2 = idx%64
        int s = idx >> 6, e2 = idx & 63;
        float2 v = xb2[idx];
        u32 hi, lo;
        split_pair(v.x, v.y, hi, lo);
        *(u32*)&X[s * XSTR + e2 * 2] = hi;
        *(u32*)&X[s * XSTR + 128 + e2 * 2] = lo;
    }
    __syncthreads();

    // ---- phase 1: QKV = X[32,128] @ Wqkv[128,384], two nj-halves for reg pressure ----
#pragma unroll
    for (int hf = 0; hf < 2; hf++) {
        float acc[2][3][4];
#pragma unroll
        for (int mt = 0; mt < 2; mt++)
#pragma unroll
            for (int nj = 0; nj < 3; nj++)
#pragma unroll
                for (int c = 0; c < 4; c++) acc[mt][nj][c] = 0.0f;

#pragma unroll
        for (int kt = 0; kt < 8; kt++) {
            u32 ah[2][4], al[2][4];
#pragma unroll
            for (int mt = 0; mt < 2; mt++) {
                const __half* pb = X + (mt * 16 + g) * XSTR + kt * 16 + 2 * tig;
                loadA(ah[mt], pb, XSTR);
                loadA(al[mt], pb + 128, XSTR);
            }
#pragma unroll
            for (int nj = 0; nj < 3; nj++) {
                int j = w * 6 + hf * 3 + nj;
                uint4 bq = __ldg(g_wqkv_i + (j * 8 + kt) * 32 + lane);
                u32 bh[2] = {bq.x, bq.y}, bl[2] = {bq.z, bq.w};
#pragma unroll
                for (int mt = 0; mt < 2; mt++) {
                    mma16816(acc[mt][nj], ah[mt], bh);
                    mma16816(acc[mt][nj], ah[mt], bl);
                    mma16816(acc[mt][nj], al[mt], bh);
                }
            }
        }
        // epilogue: split + scatter to Q/K/VT
#pragma unroll
        for (int nj = 0; nj < 3; nj++) {
            int j = w * 6 + hf * 3 + nj;
            int m = j >> 4, h = (j >> 2) & 3, dt = j & 3;
#pragma unroll
            for (int mt = 0; mt < 2; mt++) {
                float c0 = acc[mt][nj][0], c1 = acc[mt][nj][1];
                float c2 = acc[mt][nj][2], c3 = acc[mt][nj][3];
                int r0 = mt * 16 + g, r1 = r0 + 8;
                int d0 = dt * 8 + 2 * tig;
                if (m == 0) {
                    c0 *= SCALE_; c1 *= SCALE_; c2 *= SCALE_; c3 *= SCALE_;
                    u32 hi, lo;
                    split_pair(c0, c1, hi, lo);
                    *(u32*)&Q[h * QHEAD + r0 * QSTR + d0] = hi;
                    *(u32*)&Q[h * QHEAD + r0 * QSTR + 32 + d0] = lo;
                    split_pair(c2, c3, hi, lo);
                    *(u32*)&Q[h * QHEAD + r1 * QSTR + d0] = hi;
                    *(u32*)&Q[h * QHEAD + r1 * QSTR + 32 + d0] = lo;
                } else if (m == 1) {
                    u32 hi, lo;
                    split_pair(c0, c1, hi, lo);
                    *(u32*)&K[h * QHEAD + r0 * QSTR + d0] = hi;
                    *(u32*)&K[h * QHEAD + r0 * QSTR + 32 + d0] = lo;
                    split_pair(c2, c3, hi, lo);
                    *(u32*)&K[h * QHEAD + r1 * QSTR + d0] = hi;
                    *(u32*)&K[h * QHEAD + r1 * QSTR + 32 + d0] = lo;
                } else {
                    // VT[h][d][t] : row = d, col = t ; lo at col+32
                    __half* vb = VT + h * QHEAD;
                    split_one(c0, &vb[d0 * QSTR + r0],       &vb[d0 * QSTR + 32 + r0]);
                    split_one(c1, &vb[(d0 + 1) * QSTR + r0], &vb[(d0 + 1) * QSTR + 32 + r0]);
                    split_one(c2, &vb[d0 * QSTR + r1],       &vb[d0 * QSTR + 32 + r1]);
                    split_one(c3, &vb[(d0 + 1) * QSTR + r1], &vb[(d0 + 1) * QSTR + 32 + r1]);
                }
            }
        }
    }
    __syncthreads();

    // ---- phase 2: scores[h] = Q[h] @ K[h]^T ----
    {
        int h = w >> 1, mt = w & 1;
        float acc[4][4];
#pragma unroll
        for (int nt = 0; nt < 4; nt++)
#pragma unroll
            for (int c = 0; c < 4; c++) acc[nt][c] = 0.0f;
#pragma unroll
        for (int kt = 0; kt < 2; kt++) {
            u32 ah[4], al[4];
            const __half* pq = Q + h * QHEAD + (mt * 16 + g) * QSTR + kt * 16 + 2 * tig;
            loadA(ah, pq, QSTR);
            loadA(al, pq + 32, QSTR);
#pragma unroll
            for (int nt = 0; nt < 4; nt++) {
                const __half* pk = K + h * QHEAD + (nt * 8 + g) * QSTR + kt * 16 + 2 * tig;
                u32 bh[2], bl2[2];
                bh[0] = *(const u32*)pk;        bh[1] = *(const u32*)(pk + 8);
                bl2[0] = *(const u32*)(pk + 32); bl2[1] = *(const u32*)(pk + 40);
                mma16816(acc[nt], ah, bh);
                mma16816(acc[nt], ah, bl2);
                mma16816(acc[nt], al, bh);
            }
        }
        __syncthreads();  // X region -> SC region handoff
#pragma unroll
        for (int nt = 0; nt < 4; nt++) {
            float* p0 = SC + h * 1056 + (mt * 16 + g) * 33 + nt * 8 + 2 * tig;
            float* p1 = SC + h * 1056 + (mt * 16 + g + 8) * 33 + nt * 8 + 2 * tig;
            p0[0] = acc[nt][0]; p0[1] = acc[nt][1];
            p1[0] = acc[nt][2]; p1[1] = acc[nt][3];
        }
    }
    __syncthreads();

    // ---- phase 3: exact fp32 softmax -> A hi/lo (K region) ----
    if (tid < 128) {
        int h = tid >> 5, s = tid & 31;
        const float* row = SC + h * 1056 + s * 33;
        float v[32], mx = -1e30f;
#pragma unroll
        for (int t = 0; t < 32; t++) { v[t] = row[t]; mx = fmaxf(mx, v[t]); }
        float sum = 0.0f;
#pragma unroll
        for (int t = 0; t < 32; t++) { v[t] = expf(v[t] - mx); sum += v[t]; }
        float inv = 1.0f / sum;
        __half* pah = A + h * QHEAD + s * QSTR;
#pragma unroll
        for (int t = 0; t < 32; t++) split_one(v[t] * inv, &pah[t], &pah[32 + t]);
    }
    __syncthreads();

    // ---- phase 4: Hd[h] = A[h] @ V[h] -> HD [s][h*32+d] hi/lo ----
    {
        int h = w >> 1, mt = w & 1;
        float acc[4][4];
#pragma unroll
        for (int nt = 0; nt < 4; nt++)
#pragma unroll
            for (int c = 0; c < 4; c++) acc[nt][c] = 0.0f;
#pragma unroll
        for (int kt = 0; kt < 2; kt++) {
            u32 ah[4], al[4];
            const __half* pa = A + h * QHEAD + (mt * 16 + g) * QSTR + kt * 16 + 2 * tig;
            loadA(ah, pa, QSTR);
            loadA(al, pa + 32, QSTR);
#pragma unroll
            for (int nt = 0; nt < 4; nt++) {
                const __half* pv = VT + h * QHEAD + (nt * 8 + g) * QSTR + kt * 16 + 2 * tig;
                u32 bh[2], bl2[2];
                bh[0] = *(const u32*)pv;        bh[1] = *(const u32*)(pv + 8);
                bl2[0] = *(const u32*)(pv + 32); bl2[1] = *(const u32*)(pv + 40);
                mma16816(acc[nt], ah, bh);
                mma16816(acc[nt], ah, bl2);
                mma16816(acc[nt], al, bh);
            }
        }
        __syncthreads();  // SC region -> HD region handoff
#pragma unroll
        for (int nt = 0; nt < 4; nt++) {
            int col = h * 32 + nt * 8 + 2 * tig;
            int r0 = mt * 16 + g, r1 = r0 + 8;
            u32 hi, lo;
            split_pair(acc[nt][0], acc[nt][1], hi, lo);
            *(u32*)&HD[r0 * XSTR + col] = hi;
            *(u32*)&HD[r0 * XSTR + 128 + col] = lo;
            split_pair(acc[nt][2], acc[nt][3], hi, lo);
            *(u32*)&HD[r1 * XSTR + col] = hi;
            *(u32*)&HD[r1 * XSTR + 128 + col] = lo;
        }
    }
    __syncthreads();

    // ---- phase 5: out = Hd[32,128] @ WoFlat[128,128] ----
    {
        float acc[2][2][4];
#pragma unroll
        for (int mt = 0; mt < 2; mt++)
#pragma unroll
            for (int n = 0; n < 2; n++)
#pragma unroll
                for (int c = 0; c < 4; c++) acc[mt][n][c] = 0.0f;
#pragma unroll
        for (int kt = 0; kt < 8; kt++) {
            u32 ah[2][4], al[2][4];
#pragma unroll
            for (int mt = 0; mt < 2; mt++) {
                const __half* pb = HD + (mt * 16 + g) * XSTR + kt * 16 + 2 * tig;
                loadA(ah[mt], pb, XSTR);
                loadA(al[mt], pb + 128, XSTR);
            }
#pragma unroll
            for (int ntl = 0; ntl < 2; ntl++) {
                int nt = w * 2 + ntl;
                uint4 bq = __ldg(g_wo_i + (nt * 8 + kt) * 32 + lane);
                u32 bh[2] = {bq.x, bq.y}, bl2[2] = {bq.z, bq.w};
#pragma unroll
                for (int mt = 0; mt < 2; mt++) {
                    mma16816(acc[mt][ntl], ah[mt], bh);
                    mma16816(acc[mt][ntl], ah[mt], bl2);
                    mma16816(acc[mt][ntl], al[mt], bh);
                }
            }
        }
        float* ob = out + b * 4096LL;
#pragma unroll
        for (int mt = 0; mt < 2; mt++)
#pragma unroll
            for (int ntl = 0; ntl < 2; ntl++) {
                int nt = w * 2 + ntl;
                int r0 = mt * 16 + g, c = nt * 8 + 2 * tig;
                *(float2*)&ob[r0 * 128 + c] = make_float2(acc[mt][ntl][0], acc[mt][ntl][1]);
                *(float2*)&ob[(r0 + 8) * 128 + c] = make_float2(acc[mt][ntl][2], acc[mt][ntl][3]);
            }
    }
}

extern "C" void kernel_launch(void* const* d_in, const int* in_sizes, int n_in,
                              void* d_out, int out_size) {
    const float* x  = (const float*)d_in[0];
    const float* wq = (const float*)d_in[1];
    const float* wk = (const float*)d_in[2];
    const float* wv = (const float*)d_in[3];
    const float* wo = (const float*)d_in[4];
    float* out = (float*)d_out;

    cudaFuncSetAttribute(attn_mma3_kernel,
                         cudaFuncAttributeMaxDynamicSharedMemorySize, SMEM_BYTES);

    prep_weights<<<64, 256>>>(wq, wk, wv, wo);
    attn_mma3_kernel<<<NB_, 256, SMEM_BYTES>>>(x, out);
}

// round 6
// speedup vs baseline: 1.5710x; 1.5710x over previous
#include <cuda_runtime.h>
#include <cuda_fp16.h>

#define NB_ 16384
#define SCALE_ 0.17677669529663687f  // 1/sqrt(32)

typedef unsigned u32;

// ---- interleaved weight fragment buffers: uint4 = {b0_hi, b1_hi, b0_lo, b1_lo} ----
__device__ __align__(16) uint4 g_wqkv_i[48 * 8 * 32];  // 196608 B
__device__ __align__(16) uint4 g_wo_i[16 * 8 * 32];    //  65536 B

__device__ __forceinline__ void split_pair(float a, float b, u32& hi, u32& lo) {
    __half ha = __float2half_rn(a), hb = __float2half_rn(b);
    __half2 h2 = __halves2half2(ha, hb);
    hi = *(u32*)&h2;
    __half2 l2 = __floats2half2_rn(a - __half2float(ha), b - __half2float(hb));
    lo = *(u32*)&l2;
}
__device__ __forceinline__ void split_one(float v, __half* ph, __half* pl) {
    __half h = __float2half_rn(v);
    *ph = h;
    *pl = __float2half_rn(v - __half2float(h));
}
__device__ __forceinline__ u32 smem_u32(const void* p) {
    u32 a;
    asm("{ .reg .u64 t; cvta.to.shared.u64 t, %1; cvt.u32.u64 %0, t; }" : "=r"(a) : "l"(p));
    return a;
}

__device__ __forceinline__ void mma16816(float* d, const u32* a, const u32* b) {
    asm volatile(
        "mma.sync.aligned.m16n8k16.row.col.f32.f16.f16.f32 "
        "{%0,%1,%2,%3}, {%4,%5,%6,%7}, {%8,%9}, {%0,%1,%2,%3};\n"
        : "+f"(d[0]), "+f"(d[1]), "+f"(d[2]), "+f"(d[3])
        : "r"(a[0]), "r"(a[1]), "r"(a[2]), "r"(a[3]), "r"(b[0]), "r"(b[1]));
}

// ldmatrix x4: full m16k16 A-fragment in one op. Caller passes this lane's address.
__device__ __forceinline__ void ldsmA(u32* fr, u32 addr) {
    asm volatile("ldmatrix.sync.aligned.m8n8.x4.shared.b16 {%0,%1,%2,%3}, [%4];"
        : "=r"(fr[0]), "=r"(fr[1]), "=r"(fr[2]), "=r"(fr[3]) : "r"(addr));
}

// ---- prep kernel (verified in R4): 16384 jobs, one uint4 each ----
__global__ void prep_weights(const float* __restrict__ wq, const float* __restrict__ wk,
                             const float* __restrict__ wv, const float* __restrict__ wo) {
    int i = blockIdx.x * blockDim.x + threadIdx.x;
    if (i < 12288) {  // qkv: i = (j*8+kt)*32 + lane
        int lane = i & 31, kt = (i >> 5) & 7, j = i >> 8;
        int tig = lane & 3, gg = lane >> 2;
        int m = j >> 4, h = (j >> 2) & 3, dt = j & 3;
        const float* w = ((m == 0) ? wq : ((m == 1) ? wk : wv)) + h * 4096;
        int d = dt * 8 + gg;
        int e0 = kt * 16 + 2 * tig;
        u32 h0, l0, h1, l1;
        split_pair(w[e0 * 32 + d], w[(e0 + 1) * 32 + d], h0, l0);
        split_pair(w[(e0 + 8) * 32 + d], w[(e0 + 9) * 32 + d], h1, l1);
        g_wqkv_i[i] = make_uint4(h0, h1, l0, l1);
    } else if (i < 16384) {  // wo
        int k = i - 12288;
        int lane = k & 31, kt = (k >> 5) & 7, nt = k >> 8;
        int tig = lane & 3, gg = lane >> 2;
        int o = nt * 8 + gg;
        int hd0 = kt * 16 + 2 * tig;
        u32 h0, l0, h1, l1;
        split_pair(wo[hd0 * 128 + o], wo[(hd0 + 1) * 128 + o], h0, l0);
        split_pair(wo[(hd0 + 8) * 128 + o], wo[(hd0 + 9) * 128 + o], h1, l1);
        g_wo_i[k] = make_uint4(h0, h1, l0, l1);
    }
}

// ---- R2 smem layout (bytes) ----
#define OFF_XH 0
#define OFF_XL 8704
#define OFF_QH 17408
#define OFF_QL 27648
#define OFF_KH 37888
#define OFF_KL 48128
#define OFF_VTH 58368
#define OFF_VTL 68608
#define OFF_SC 78848
#define SMEM_BYTES 95744

extern __shared__ char smem_raw[];

__global__ __launch_bounds__(256, 2)
void attn_mma_kernel(const float* __restrict__ x, float* __restrict__ out) {
    __half* XH = (__half*)(smem_raw + OFF_XH);
    __half* XL = (__half*)(smem_raw + OFF_XL);
    __half* QH = (__half*)(smem_raw + OFF_QH);
    __half* QL = (__half*)(smem_raw + OFF_QL);
    __half* KH = (__half*)(smem_raw + OFF_KH);
    __half* KL = (__half*)(smem_raw + OFF_KL);
    __half* VTH = (__half*)(smem_raw + OFF_VTH);
    __half* VTL = (__half*)(smem_raw + OFF_VTL);
    float* SC = (float*)(smem_raw + OFF_SC);
    __half* AH = KH;   // reuse after phase 2
    __half* AL = KL;
    __half* HDH = XH;  // reuse after phase 1
    __half* HDL = XL;

    const int tid = threadIdx.x;
    const int lane = tid & 31, w = tid >> 5;
    const int g = lane >> 2, tig = lane & 3;
    const long long b = blockIdx.x;
    const u32 sb = smem_u32(smem_raw);

    // ldmatrix per-lane row/col offsets (standard x4 tiling: m0=r0-7/k0-7, m1=r8-15/k0-7, m2=r0-7/k8-15, m3=r8-15/k8-15)
    const int q4 = lane >> 3;
    const int lrow = (lane & 7) + ((q4 & 1) << 3);
    const int lcol = (q4 & 2) << 2;  // 0 or 8 halfs

    // ---- load x, split fp16 hi/lo ----
    const float2* xb2 = (const float2*)(x + b * 4096LL);
#pragma unroll
    for (int i = 0; i < 8; i++) {
        int idx = tid + i * 256;  // s = idx/64, e2 = idx%64
        int s = idx >> 6, e2 = idx & 63;
        float2 v = xb2[idx];
        u32 hi, lo;
        split_pair(v.x, v.y, hi, lo);
        *(u32*)&XH[s * 136 + e2 * 2] = hi;
        *(u32*)&XL[s * 136 + e2 * 2] = lo;
    }
    __syncthreads();

    // ---- phase 1: QKV = X[32,128] @ Wqkv[128,384] ----
    {
        float acc[2][6][4];
#pragma unroll
        for (int mt = 0; mt < 2; mt++)
#pragma unroll
            for (int nj = 0; nj < 6; nj++)
#pragma unroll
                for (int c = 0; c < 4; c++) acc[mt][nj][c] = 0.0f;

#pragma unroll
        for (int kt = 0; kt < 8; kt++) {
            u32 ah[2][4], al[2][4];
#pragma unroll
            for (int mt = 0; mt < 2; mt++) {
                u32 a0 = sb + OFF_XH + ((mt * 16 + lrow) * 136 + kt * 16 + lcol) * 2;
                ldsmA(ah[mt], a0);
                ldsmA(al[mt], a0 + (OFF_XL - OFF_XH));
            }
#pragma unroll
            for (int nj = 0; nj < 6; nj++) {
                int j = w * 6 + nj;
                uint4 bq = __ldg(g_wqkv_i + (j * 8 + kt) * 32 + lane);
                u32 bh[2] = {bq.x, bq.y}, bl[2] = {bq.z, bq.w};
#pragma unroll
                for (int mt = 0; mt < 2; mt++) {
                    mma16816(acc[mt][nj], ah[mt], bh);
                    mma16816(acc[mt][nj], ah[mt], bl);
                    mma16816(acc[mt][nj], al[mt], bh);
                }
            }
        }
        // epilogue: split + scatter to Q/K/VT
#pragma unroll
        for (int nj = 0; nj < 6; nj++) {
            int j = w * 6 + nj;
            int m = j >> 4, h = (j >> 2) & 3, dt = j & 3;
#pragma unroll
            for (int mt = 0; mt < 2; mt++) {
                float c0 = acc[mt][nj][0], c1 = acc[mt][nj][1];
                float c2 = acc[mt][nj][2], c3 = acc[mt][nj][3];
                int r0 = mt * 16 + g, r1 = r0 + 8;
                int d0 = dt * 8 + 2 * tig;
                if (m == 0) {
                    c0 *= SCALE_; c1 *= SCALE_; c2 *= SCALE_; c3 *= SCALE_;
                    u32 hi, lo;
                    split_pair(c0, c1, hi, lo);
                    *(u32*)&QH[h * 1280 + r0 * 40 + d0] = hi;
                    *(u32*)&QL[h * 1280 + r0 * 40 + d0] = lo;
                    split_pair(c2, c3, hi, lo);
                    *(u32*)&QH[h * 1280 + r1 * 40 + d0] = hi;
                    *(u32*)&QL[h * 1280 + r1 * 40 + d0] = lo;
                } else if (m == 1) {
                    u32 hi, lo;
                    split_pair(c0, c1, hi, lo);
                    *(u32*)&KH[h * 1280 + r0 * 40 + d0] = hi;
                    *(u32*)&KL[h * 1280 + r0 * 40 + d0] = lo;
                    split_pair(c2, c3, hi, lo);
                    *(u32*)&KH[h * 1280 + r1 * 40 + d0] = hi;
                    *(u32*)&KL[h * 1280 + r1 * 40 + d0] = lo;
                } else {
                    split_one(c0, &VTH[h * 1280 + d0 * 40 + r0], &VTL[h * 1280 + d0 * 40 + r0]);
                    split_one(c1, &VTH[h * 1280 + (d0 + 1) * 40 + r0], &VTL[h * 1280 + (d0 + 1) * 40 + r0]);
                    split_one(c2, &VTH[h * 1280 + d0 * 40 + r1], &VTL[h * 1280 + d0 * 40 + r1]);
                    split_one(c3, &VTH[h * 1280 + (d0 + 1) * 40 + r1], &VTL[h * 1280 + (d0 + 1) * 40 + r1]);
                }
            }
        }
    }
    __syncthreads();

    // ---- phase 2: scores[h] = Q[h] @ K[h]^T ----
    {
        int h = w >> 1, mt = w & 1;
        float acc[4][4];
#pragma unroll
        for (int nt = 0; nt < 4; nt++)
#pragma unroll
            for (int c = 0; c < 4; c++) acc[nt][c] = 0.0f;
#pragma unroll
        for (int kt = 0; kt < 2; kt++) {
            u32 ah[4], al[4];
            u32 a0 = sb + OFF_QH + (h * 1280 + (mt * 16 + lrow) * 40 + kt * 16 + lcol) * 2;
            ldsmA(ah, a0);
            ldsmA(al, a0 + (OFF_QL - OFF_QH));
#pragma unroll
            for (int nt = 0; nt < 4; nt++) {
                const __half* pk = KH + h * 1280 + (nt * 8 + g) * 40 + kt * 16 + 2 * tig;
                u32 bh[2], bl2[2];
                bh[0] = *(const u32*)pk;          bh[1] = *(const u32*)(pk + 8);
                bl2[0] = *(const u32*)(pk + 5120); bl2[1] = *(const u32*)(pk + 5128);
                mma16816(acc[nt], ah, bh);
                mma16816(acc[nt], ah, bl2);
                mma16816(acc[nt], al, bh);
            }
        }
#pragma unroll
        for (int nt = 0; nt < 4; nt++) {
            float* p0 = SC + h * 1056 + (mt * 16 + g) * 33 + nt * 8 + 2 * tig;
            float* p1 = SC + h * 1056 + (mt * 16 + g + 8) * 33 + nt * 8 + 2 * tig;
            p0[0] = acc[nt][0]; p0[1] = acc[nt][1];
            p1[0] = acc[nt][2]; p1[1] = acc[nt][3];
        }
    }
    __syncthreads();

    // ---- phase 3: exact fp32 softmax, 256 threads (2 per row, 16 elems each) ----
    {
        int row = tid >> 1, hf = tid & 1;  // row = h*32+s
        const float* rp = SC + (row >> 5) * 1056 + (row & 31) * 33 + hf * 16;
        float v[16], mx = -1e30f;
#pragma unroll
        for (int t = 0; t < 16; t++) { v[t] = rp[t]; mx = fmaxf(mx, v[t]); }
        mx = fmaxf(mx, __shfl_xor_sync(0xFFFFFFFF, mx, 1));
        float sum = 0.0f;
#pragma unroll
        for (int t = 0; t < 16; t++) { v[t] = expf(v[t] - mx); sum += v[t]; }
        sum += __shfl_xor_sync(0xFFFFFFFF, sum, 1);
        float inv = 1.0f / sum;
        __half* pah = AH + (row >> 5) * 1280 + (row & 31) * 40 + hf * 16;
        __half* pal = AL + (row >> 5) * 1280 + (row & 31) * 40 + hf * 16;
#pragma unroll
        for (int t = 0; t < 16; t++) split_one(v[t] * inv, &pah[t], &pal[t]);
    }
    __syncthreads();

    // ---- phase 4: Hd[h] = A[h] @ V[h] -> HDH/HDL [s][h*32+d] ----
    {
        int h = w >> 1, mt = w & 1;
        float acc[4][4];
#pragma unroll
        for (int nt = 0; nt < 4; nt++)
#pragma unroll
            for (int c = 0; c < 4; c++) acc[nt][c] = 0.0f;
#pragma unroll
        for (int kt = 0; kt < 2; kt++) {
            u32 ah[4], al[4];
            u32 a0 = sb + OFF_KH + (h * 1280 + (mt * 16 + lrow) * 40 + kt * 16 + lcol) * 2;
            ldsmA(ah, a0);
            ldsmA(al, a0 + (OFF_KL - OFF_KH));
#pragma unroll
            for (int nt = 0; nt < 4; nt++) {
                const __half* pv = VTH + h * 1280 + (nt * 8 + g) * 40 + kt * 16 + 2 * tig;
                u32 bh[2], bl2[2];
                bh[0] = *(const u32*)pv;          bh[1] = *(const u32*)(pv + 8);
                bl2[0] = *(const u32*)(pv + 5120); bl2[1] = *(const u32*)(pv + 5128);
                mma16816(acc[nt], ah, bh);
                mma16816(acc[nt], ah, bl2);
                mma16816(acc[nt], al, bh);
            }
        }
#pragma unroll
        for (int nt = 0; nt < 4; nt++) {
            int col = h * 32 + nt * 8 + 2 * tig;
            int r0 = mt * 16 + g, r1 = r0 + 8;
            u32 hi, lo;
            split_pair(acc[nt][0], acc[nt][1], hi, lo);
            *(u32*)&HDH[r0 * 136 + col] = hi;
            *(u32*)&HDL[r0 * 136 + col] = lo;
            split_pair(acc[nt][2], acc[nt][3], hi, lo);
            *(u32*)&HDH[r1 * 136 + col] = hi;
            *(u32*)&HDL[r1 * 136 + col] = lo;
        }
    }
    __syncthreads();

    // ---- phase 5: out = Hd[32,128] @ WoFlat[128,128] ----
    {
        float acc[2][2][4];
#pragma unroll
        for (int mt = 0; mt < 2; mt++)
#pragma unroll
            for (int n = 0; n < 2; n++)
#pragma unroll
                for (int c = 0; c < 4; c++) acc[mt][n][c] = 0.0f;
#pragma unroll
        for (int kt = 0; kt < 8; kt++) {
            u32 ah[2][4], al[2][4];
#pragma unroll
            for (int mt = 0; mt < 2; mt++) {
                u32 a0 = sb + OFF_XH + ((mt * 16 + lrow) * 136 + kt * 16 + lcol) * 2;
                ldsmA(ah[mt], a0);
                ldsmA(al[mt], a0 + (OFF_XL - OFF_XH));
            }
#pragma unroll
            for (int ntl = 0; ntl < 2; ntl++) {
                int nt = w * 2 + ntl;
                uint4 bq = __ldg(g_wo_i + (nt * 8 + kt) * 32 + lane);
                u32 bh[2] = {bq.x, bq.y}, bl2[2] = {bq.z, bq.w};
#pragma unroll
                for (int mt = 0; mt < 2; mt++) {
                    mma16816(acc[mt][ntl], ah[mt], bh);
                    mma16816(acc[mt][ntl], ah[mt], bl2);
                    mma16816(acc[mt][ntl], al[mt], bh);
                }
            }
        }
        float* ob = out + b * 4096LL;
#pragma unroll
        for (int mt = 0; mt < 2; mt++)
#pragma unroll
            for (int ntl = 0; ntl < 2; ntl++) {
                int nt = w * 2 + ntl;
                int r0 = mt * 16 + g, c = nt * 8 + 2 * tig;
                *(float2*)&ob[r0 * 128 + c] = make_float2(acc[mt][ntl][0], acc[mt][ntl][1]);
                *(float2*)&ob[(r0 + 8) * 128 + c] = make_float2(acc[mt][ntl][2], acc[mt][ntl][3]);
            }
    }
}

extern "C" void kernel_launch(void* const* d_in, const int* in_sizes, int n_in,
                              void* d_out, int out_size) {
    const float* x  = (const float*)d_in[0];
    const float* wq = (const float*)d_in[1];
    const float* wk = (const float*)d_in[2];
    const float* wv = (const float*)d_in[3];
    const float* wo = (const float*)d_in[4];
    float* out = (float*)d_out;

    cudaFuncSetAttribute(attn_mma_kernel,
                         cudaFuncAttributeMaxDynamicSharedMemorySize, SMEM_BYTES);

    prep_weights<<<64, 256>>>(wq, wk, wv, wo);
    attn_mma_kernel<<<NB_, 256, SMEM_BYTES>>>(x, out);
}

// round 7
// speedup vs baseline: 1.7518x; 1.1151x over previous
#include <cuda_runtime.h>
#include <cuda_fp16.h>

#define NB_ 16384
#define SCALE_ 0.17677669529663687f  // 1/sqrt(32)

typedef unsigned u32;

// ---- interleaved weight fragment buffers: uint4 = {b0_hi, b1_hi, b0_lo, b1_lo} ----
__device__ __align__(16) uint4 g_wqkv_i[48 * 8 * 32];  // 196608 B
__device__ __align__(16) uint4 g_wo_i[16 * 8 * 32];    //  65536 B

__device__ __forceinline__ void split_pair(float a, float b, u32& hi, u32& lo) {
    __half ha = __float2half_rn(a), hb = __float2half_rn(b);
    __half2 h2 = __halves2half2(ha, hb);
    hi = *(u32*)&h2;
    __half2 l2 = __floats2half2_rn(a - __half2float(ha), b - __half2float(hb));
    lo = *(u32*)&l2;
}
__device__ __forceinline__ void split_one(float v, __half* ph, __half* pl) {
    __half h = __float2half_rn(v);
    *ph = h;
    *pl = __float2half_rn(v - __half2float(h));
}
__device__ __forceinline__ u32 smem_u32(const void* p) {
    u32 a;
    asm("{ .reg .u64 t; cvta.to.shared.u64 t, %1; cvt.u32.u64 %0, t; }" : "=r"(a) : "l"(p));
    return a;
}

__device__ __forceinline__ void mma16816(float* d, const u32* a, const u32* b) {
    asm volatile(
        "mma.sync.aligned.m16n8k16.row.col.f32.f16.f16.f32 "
        "{%0,%1,%2,%3}, {%4,%5,%6,%7}, {%8,%9}, {%0,%1,%2,%3};\n"
        : "+f"(d[0]), "+f"(d[1]), "+f"(d[2]), "+f"(d[3])
        : "r"(a[0]), "r"(a[1]), "r"(a[2]), "r"(a[3]), "r"(b[0]), "r"(b[1]));
}

// ldmatrix x4: full m16k16 A-fragment in one op.
__device__ __forceinline__ void ldsmA(u32* fr, u32 addr) {
    asm volatile("ldmatrix.sync.aligned.m8n8.x4.shared.b16 {%0,%1,%2,%3}, [%4];"
        : "=r"(fr[0]), "=r"(fr[1]), "=r"(fr[2]), "=r"(fr[3]) : "r"(addr));
}

// ---- prep kernel (verified): 16384 jobs, one uint4 each ----
__global__ void prep_weights(const float* __restrict__ wq, const float* __restrict__ wk,
                             const float* __restrict__ wv, const float* __restrict__ wo) {
    int i = blockIdx.x * blockDim.x + threadIdx.x;
    if (i < 12288) {  // qkv: i = (j*8+kt)*32 + lane
        int lane = i & 31, kt = (i >> 5) & 7, j = i >> 8;
        int tig = lane & 3, gg = lane >> 2;
        int m = j >> 4, h = (j >> 2) & 3, dt = j & 3;
        const float* w = ((m == 0) ? wq : ((m == 1) ? wk : wv)) + h * 4096;
        int d = dt * 8 + gg;
        int e0 = kt * 16 + 2 * tig;
        u32 h0, l0, h1, l1;
        split_pair(w[e0 * 32 + d], w[(e0 + 1) * 32 + d], h0, l0);
        split_pair(w[(e0 + 8) * 32 + d], w[(e0 + 9) * 32 + d], h1, l1);
        g_wqkv_i[i] = make_uint4(h0, h1, l0, l1);
    } else if (i < 16384) {  // wo
        int k = i - 12288;
        int lane = k & 31, kt = (k >> 5) & 7, nt = k >> 8;
        int tig = lane & 3, gg = lane >> 2;
        int o = nt * 8 + gg;
        int hd0 = kt * 16 + 2 * tig;
        u32 h0, l0, h1, l1;
        split_pair(wo[hd0 * 128 + o], wo[(hd0 + 1) * 128 + o], h0, l0);
        split_pair(wo[(hd0 + 8) * 128 + o], wo[(hd0 + 9) * 128 + o], h1, l1);
        g_wo_i[k] = make_uint4(h0, h1, l0, l1);
    }
}

// ---- smem layout (bytes); SC eliminated (softmax lives in registers now) ----
#define OFF_XH 0
#define OFF_XL 8704
#define OFF_QH 17408
#define OFF_QL 27648
#define OFF_KH 37888
#define OFF_KL 48128
#define OFF_VTH 58368
#define OFF_VTL 68608
#define SMEM_BYTES 78848

extern __shared__ char smem_raw[];

__global__ __launch_bounds__(256, 2)
void attn_mma_kernel(const float* __restrict__ x, float* __restrict__ out) {
    __half* XH = (__half*)(smem_raw + OFF_XH);
    __half* XL = (__half*)(smem_raw + OFF_XL);
    __half* QH = (__half*)(smem_raw + OFF_QH);
    __half* QL = (__half*)(smem_raw + OFF_QL);
    __half* KH = (__half*)(smem_raw + OFF_KH);
    __half* KL = (__half*)(smem_raw + OFF_KL);
    __half* VTH = (__half*)(smem_raw + OFF_VTH);
    __half* VTL = (__half*)(smem_raw + OFF_VTL);
    __half* HDH = XH;  // reuse after phase 1
    __half* HDL = XL;

    const int tid = threadIdx.x;
    const int lane = tid & 31, w = tid >> 5;
    const int g = lane >> 2, tig = lane & 3;
    const long long b = blockIdx.x;
    const u32 sb = smem_u32(smem_raw);

    // ldmatrix per-lane address offsets
    const int q4 = lane >> 3;
    const int lrow = (lane & 7) + ((q4 & 1) << 3);
    const int lcol = (q4 & 2) << 2;  // 0 or 8 halfs

    // ---- load x, split fp16 hi/lo ----
    const float2* xb2 = (const float2*)(x + b * 4096LL);
#pragma unroll
    for (int i = 0; i < 8; i++) {
        int idx = tid + i * 256;  // s = idx/64, e2 = idx%64
        int s = idx >> 6, e2 = idx & 63;
        float2 v = xb2[idx];
        u32 hi, lo;
        split_pair(v.x, v.y, hi, lo);
        *(u32*)&XH[s * 136 + e2 * 2] = hi;
        *(u32*)&XL[s * 136 + e2 * 2] = lo;
    }
    __syncthreads();

    // ---- phase 1: QKV = X[32,128] @ Wqkv[128,384] ----
    {
        float acc[2][6][4];
#pragma unroll
        for (int mt = 0; mt < 2; mt++)
#pragma unroll
            for (int nj = 0; nj < 6; nj++)
#pragma unroll
                for (int c = 0; c < 4; c++) acc[mt][nj][c] = 0.0f;

#pragma unroll
        for (int kt = 0; kt < 8; kt++) {
            u32 ah[2][4], al[2][4];
#pragma unroll
            for (int mt = 0; mt < 2; mt++) {
                u32 a0 = sb + OFF_XH + ((mt * 16 + lrow) * 136 + kt * 16 + lcol) * 2;
                ldsmA(ah[mt], a0);
                ldsmA(al[mt], a0 + (OFF_XL - OFF_XH));
            }
#pragma unroll
            for (int nj = 0; nj < 6; nj++) {
                int j = w * 6 + nj;
                uint4 bq = __ldg(g_wqkv_i + (j * 8 + kt) * 32 + lane);
                u32 bh[2] = {bq.x, bq.y}, bl[2] = {bq.z, bq.w};
#pragma unroll
                for (int mt = 0; mt < 2; mt++) {
                    mma16816(acc[mt][nj], ah[mt], bh);
                    mma16816(acc[mt][nj], ah[mt], bl);
                    mma16816(acc[mt][nj], al[mt], bh);
                }
            }
        }
        // epilogue: split + scatter to Q/K/VT
#pragma unroll
        for (int nj = 0; nj < 6; nj++) {
            int j = w * 6 + nj;
            int m = j >> 4, h = (j >> 2) & 3, dt = j & 3;
#pragma unroll
            for (int mt = 0; mt < 2; mt++) {
                float c0 = acc[mt][nj][0], c1 = acc[mt][nj][1];
                float c2 = acc[mt][nj][2], c3 = acc[mt][nj][3];
                int r0 = mt * 16 + g, r1 = r0 + 8;
                int d0 = dt * 8 + 2 * tig;
                if (m == 0) {
                    c0 *= SCALE_; c1 *= SCALE_; c2 *= SCALE_; c3 *= SCALE_;
                    u32 hi, lo;
                    split_pair(c0, c1, hi, lo);
                    *(u32*)&QH[h * 1280 + r0 * 40 + d0] = hi;
                    *(u32*)&QL[h * 1280 + r0 * 40 + d0] = lo;
                    split_pair(c2, c3, hi, lo);
                    *(u32*)&QH[h * 1280 + r1 * 40 + d0] = hi;
                    *(u32*)&QL[h * 1280 + r1 * 40 + d0] = lo;
                } else if (m == 1) {
                    u32 hi, lo;
                    split_pair(c0, c1, hi, lo);
                    *(u32*)&KH[h * 1280 + r0 * 40 + d0] = hi;
                    *(u32*)&KL[h * 1280 + r0 * 40 + d0] = lo;
                    split_pair(c2, c3, hi, lo);
                    *(u32*)&KH[h * 1280 + r1 * 40 + d0] = hi;
                    *(u32*)&KL[h * 1280 + r1 * 40 + d0] = lo;
                } else {
                    split_one(c0, &VTH[h * 1280 + d0 * 40 + r0], &VTL[h * 1280 + d0 * 40 + r0]);
                    split_one(c1, &VTH[h * 1280 + (d0 + 1) * 40 + r0], &VTL[h * 1280 + (d0 + 1) * 40 + r0]);
                    split_one(c2, &VTH[h * 1280 + d0 * 40 + r1], &VTL[h * 1280 + d0 * 40 + r1]);
                    split_one(c3, &VTH[h * 1280 + (d0 + 1) * 40 + r1], &VTL[h * 1280 + (d0 + 1) * 40 + r1]);
                }
            }
        }
    }
    __syncthreads();

    // ---- fused phases 2+3+4 (register-resident, warp-local, no barriers) ----
    // Warp w: head h = w>>1, row block mt = w&1 (rows mt*16+g, mt*16+8+g).
    // D-fragment layout == A-fragment layout, so softmaxed scores feed ph4 directly.
    {
        int h = w >> 1, mt = w & 1;
        float acc[4][4];
#pragma unroll
        for (int nt = 0; nt < 4; nt++)
#pragma unroll
            for (int c = 0; c < 4; c++) acc[nt][c] = 0.0f;

        // phase 2: scores = Q @ K^T
#pragma unroll
        for (int kt = 0; kt < 2; kt++) {
            u32 qh[4], ql[4];
            u32 a0 = sb + OFF_QH + (h * 1280 + (mt * 16 + lrow) * 40 + kt * 16 + lcol) * 2;
            ldsmA(qh, a0);
            ldsmA(ql, a0 + (OFF_QL - OFF_QH));
#pragma unroll
            for (int nt = 0; nt < 4; nt++) {
                const __half* pk = KH + h * 1280 + (nt * 8 + g) * 40 + kt * 16 + 2 * tig;
                u32 bh[2], bl2[2];
                bh[0] = *(const u32*)pk;          bh[1] = *(const u32*)(pk + 8);
                bl2[0] = *(const u32*)(pk + 5120); bl2[1] = *(const u32*)(pk + 5128);
                mma16816(acc[nt], qh, bh);
                mma16816(acc[nt], qh, bl2);
                mma16816(acc[nt], ql, bh);
            }
        }

        // phase 3: softmax in registers. Row r0 = mt*16+g lives in c={0,1} of lanes 4g..4g+3;
        // row r1 = r0+8 in c={2,3}. Quad shfl reduction over tig.
        float mx0 = -1e30f, mx1 = -1e30f;
#pragma unroll
        for (int nt = 0; nt < 4; nt++) {
            mx0 = fmaxf(mx0, fmaxf(acc[nt][0], acc[nt][1]));
            mx1 = fmaxf(mx1, fmaxf(acc[nt][2], acc[nt][3]));
        }
        mx0 = fmaxf(mx0, __shfl_xor_sync(0xFFFFFFFF, mx0, 1));
        mx0 = fmaxf(mx0, __shfl_xor_sync(0xFFFFFFFF, mx0, 2));
        mx1 = fmaxf(mx1, __shfl_xor_sync(0xFFFFFFFF, mx1, 1));
        mx1 = fmaxf(mx1, __shfl_xor_sync(0xFFFFFFFF, mx1, 2));
        float s0 = 0.0f, s1 = 0.0f;
#pragma unroll
        for (int nt = 0; nt < 4; nt++) {
            acc[nt][0] = __expf(acc[nt][0] - mx0); s0 += acc[nt][0];
            acc[nt][1] = __expf(acc[nt][1] - mx0); s0 += acc[nt][1];
            acc[nt][2] = __expf(acc[nt][2] - mx1); s1 += acc[nt][2];
            acc[nt][3] = __expf(acc[nt][3] - mx1); s1 += acc[nt][3];
        }
        s0 += __shfl_xor_sync(0xFFFFFFFF, s0, 1);
        s0 += __shfl_xor_sync(0xFFFFFFFF, s0, 2);
        s1 += __shfl_xor_sync(0xFFFFFFFF, s1, 1);
        s1 += __shfl_xor_sync(0xFFFFFFFF, s1, 2);
        float i0 = 1.0f / s0, i1 = 1.0f / s1;

        // reinterpret normalized scores as A-fragments (hi/lo split)
        u32 aah[2][4], aal[2][4];
#pragma unroll
        for (int kt = 0; kt < 2; kt++) {
            split_pair(acc[2 * kt][0] * i0,     acc[2 * kt][1] * i0,     aah[kt][0], aal[kt][0]);
            split_pair(acc[2 * kt][2] * i1,     acc[2 * kt][3] * i1,     aah[kt][1], aal[kt][1]);
            split_pair(acc[2 * kt + 1][0] * i0, acc[2 * kt + 1][1] * i0, aah[kt][2], aal[kt][2]);
            split_pair(acc[2 * kt + 1][2] * i1, acc[2 * kt + 1][3] * i1, aah[kt][3], aal[kt][3]);
        }

        // phase 4: Hd = A @ V  (V^T tiles from smem as B operand)
        float hd[4][4];
#pragma unroll
        for (int nt = 0; nt < 4; nt++)
#pragma unroll
            for (int c = 0; c < 4; c++) hd[nt][c] = 0.0f;
#pragma unroll
        for (int kt = 0; kt < 2; kt++) {
#pragma unroll
            for (int nt = 0; nt < 4; nt++) {
                const __half* pv = VTH + h * 1280 + (nt * 8 + g) * 40 + kt * 16 + 2 * tig;
                u32 bh[2], bl2[2];
                bh[0] = *(const u32*)pv;          bh[1] = *(const u32*)(pv + 8);
                bl2[0] = *(const u32*)(pv + 5120); bl2[1] = *(const u32*)(pv + 5128);
                mma16816(hd[nt], aah[kt], bh);
                mma16816(hd[nt], aah[kt], bl2);
                mma16816(hd[nt], aal[kt], bh);
            }
        }
        // epilogue -> HDH/HDL [s][h*32+d] (X region; X is dead for all warps post-ph1 sync)
#pragma unroll
        for (int nt = 0; nt < 4; nt++) {
            int col = h * 32 + nt * 8 + 2 * tig;
            int r0 = mt * 16 + g, r1 = r0 + 8;
            u32 hi, lo;
            split_pair(hd[nt][0], hd[nt][1], hi, lo);
            *(u32*)&HDH[r0 * 136 + col] = hi;
            *(u32*)&HDL[r0 * 136 + col] = lo;
            split_pair(hd[nt][2], hd[nt][3], hi, lo);
            *(u32*)&HDH[r1 * 136 + col] = hi;
            *(u32*)&HDL[r1 * 136 + col] = lo;
        }
    }
    __syncthreads();

    // ---- phase 5: out = Hd[32,128] @ WoFlat[128,128] ----
    {
        float acc[2][2][4];
#pragma unroll
        for (int mt = 0; mt < 2; mt++)
#pragma unroll
            for (int n = 0; n < 2; n++)
#pragma unroll
                for (int c = 0; c < 4; c++) acc[mt][n][c] = 0.0f;
#pragma unroll
        for (int kt = 0; kt < 8; kt++) {
            u32 ah[2][4], al[2][4];
#pragma unroll
            for (int mt = 0; mt < 2; mt++) {
                u32 a0 = sb + OFF_XH + ((mt * 16 + lrow) * 136 + kt * 16 + lcol) * 2;
                ldsmA(ah[mt], a0);
                ldsmA(al[mt], a0 + (OFF_XL - OFF_XH));
            }
#pragma unroll
            for (int ntl = 0; ntl < 2; ntl++) {
                int nt = w * 2 + ntl;
                uint4 bq = __ldg(g_wo_i + (nt * 8 + kt) * 32 + lane);
                u32 bh[2] = {bq.x, bq.y}, bl2[2] = {bq.z, bq.w};
#pragma unroll
                for (int mt = 0; mt < 2; mt++) {
                    mma16816(acc[mt][ntl], ah[mt], bh);
                    mma16816(acc[mt][ntl], ah[mt], bl2);
                    mma16816(acc[mt][ntl], al[mt], bh);
                }
            }
        }
        float* ob = out + b * 4096LL;
#pragma unroll
        for (int mt = 0; mt < 2; mt++)
#pragma unroll
            for (int ntl = 0; ntl < 2; ntl++) {
                int nt = w * 2 + ntl;
                int r0 = mt * 16 + g, c = nt * 8 + 2 * tig;
                *(float2*)&ob[r0 * 128 + c] = make_float2(acc[mt][ntl][0], acc[mt][ntl][1]);
                *(float2*)&ob[(r0 + 8) * 128 + c] = make_float2(acc[mt][ntl][2], acc[mt][ntl][3]);
            }
    }
}

extern "C" void kernel_launch(void* const* d_in, const int* in_sizes, int n_in,
                              void* d_out, int out_size) {
    const float* x  = (const float*)d_in[0];
    const float* wq = (const float*)d_in[1];
    const float* wk = (const float*)d_in[2];
    const float* wv = (const float*)d_in[3];
    const float* wo = (const float*)d_in[4];
    float* out = (float*)d_out;

    cudaFuncSetAttribute(attn_mma_kernel,
                         cudaFuncAttributeMaxDynamicSharedMemorySize, SMEM_BYTES);

    prep_weights<<<64, 256>>>(wq, wk, wv, wo);
    attn_mma_kernel<<<NB_, 256, SMEM_BYTES>>>(x, out);
}